// round 10
// baseline (speedup 1.0000x reference)
#include <cuda_runtime.h>
#include <cuda_fp16.h>
#include <math.h>
#include <stdint.h>

#define B_DIM 2
#define NUM_HEADS 32
#define NUM_KV 8
#define SEQ 2048
#define DM 2048
#define HD 64
#define MTOT (B_DIM * SEQ)

// fp16 scratch (allocation-free device globals)
__device__ __half g_xh[(size_t)MTOT * DM];
__device__ __half g_wq[(size_t)DM * DM];
__device__ __half g_wk[(size_t)DM * 512];
__device__ __half g_wv[(size_t)DM * 512];
__device__ __half g_wo[(size_t)DM * DM];
__device__ __half g_q[(size_t)B_DIM * NUM_HEADS * SEQ * HD];
__device__ __half g_k[(size_t)B_DIM * NUM_KV * SEQ * HD];
__device__ __half g_v[(size_t)B_DIM * NUM_KV * SEQ * HD];
__device__ __half g_ao[(size_t)MTOT * DM];
__device__ float  g_rope[SEQ * 32 * 2];

// softmax scale folded into Q at projection time: 1/sqrt(64) * log2(e)
#define QSCALE 0.1803368801111204f

// ---------------------------------------------------------------------------
// Fused prologue: all fp32->fp16 conversions + RoPE table in ONE launch.
// ---------------------------------------------------------------------------
__global__ void prep(const float4* __restrict__ x, const float4* __restrict__ wq,
                     const float4* __restrict__ wk, const float4* __restrict__ wv,
                     const float4* __restrict__ wo)
{
    const int b = blockIdx.x, tid = threadIdx.x;
    const float4* src;
    __half* dst;
    int base;
    if (b < 8192)       { src = x;  dst = g_xh; base = 0; }
    else if (b < 12288) { src = wq; dst = g_wq; base = 8192; }
    else if (b < 13312) { src = wk; dst = g_wk; base = 12288; }
    else if (b < 14336) { src = wv; dst = g_wv; base = 13312; }
    else if (b < 18432) { src = wo; dst = g_wo; base = 14336; }
    else {
        int i = (b - 18432) * 256 + tid;
        int s = i >> 5, j = i & 31;
        float inv = expf(-(float)j * 0.28782313662425572f);
        float sv, cv;
        sincosf((float)s * inv, &sv, &cv);
        g_rope[(size_t)i * 2 + 0] = cv;
        g_rope[(size_t)i * 2 + 1] = sv;
        return;
    }
    size_t i = (size_t)(b - base) * 256 + tid;
    float4 v = src[i];
    __half2* d = (__half2*)(dst + i * 4);
    d[0] = __floats2half2_rn(v.x, v.y);
    d[1] = __floats2half2_rn(v.z, v.w);
}

// ---------------------------------------------------------------------------
// Helpers
// ---------------------------------------------------------------------------
__device__ __forceinline__ uint32_t smem_u32(const void* p)
{
    return (uint32_t)__cvta_generic_to_shared(p);
}
__device__ __forceinline__ void ldmx4(uint32_t* r, uint32_t a)
{
    asm volatile("ldmatrix.sync.aligned.m8n8.x4.shared.b16 {%0,%1,%2,%3}, [%4];"
                 : "=r"(r[0]), "=r"(r[1]), "=r"(r[2]), "=r"(r[3]) : "r"(a));
}
__device__ __forceinline__ void ldmx4t(uint32_t* r, uint32_t a)
{
    asm volatile("ldmatrix.sync.aligned.m8n8.x4.trans.shared.b16 {%0,%1,%2,%3}, [%4];"
                 : "=r"(r[0]), "=r"(r[1]), "=r"(r[2]), "=r"(r[3]) : "r"(a));
}
__device__ __forceinline__ void mma_f16(float* c, const uint32_t* a, const uint32_t* b)
{
    asm volatile(
        "mma.sync.aligned.m16n8k16.row.col.f32.f16.f16.f32 "
        "{%0,%1,%2,%3}, {%4,%5,%6,%7}, {%8,%9}, {%0,%1,%2,%3};"
        : "+f"(c[0]), "+f"(c[1]), "+f"(c[2]), "+f"(c[3])
        : "r"(a[0]), "r"(a[1]), "r"(a[2]), "r"(a[3]), "r"(b[0]), "r"(b[1]));
}
__device__ __forceinline__ void cp16(uint32_t saddr, const void* g)
{
    asm volatile("cp.async.cg.shared.global [%0], [%1], 16;" :: "r"(saddr), "l"(g));
}
#define CP_COMMIT() asm volatile("cp.async.commit_group;")
#define CP_WAIT(n)  asm volatile("cp.async.wait_group %0;" :: "n"(n))

__device__ __forceinline__ float ex2(float x)
{
    float r;
    asm("ex2.approx.ftz.f32 %0, %1;" : "=f"(r) : "f"(x));
    return r;
}
__device__ __forceinline__ uint32_t ex2h2(uint32_t x)
{
    uint32_t r;
    asm("ex2.approx.f16x2 %0, %1;" : "=r"(r) : "r"(x));
    return r;
}
__device__ __forceinline__ uint32_t packh2(float lo, float hi)
{
    __half2 h = __floats2half2_rn(lo, hi);
    return *reinterpret_cast<uint32_t*>(&h);
}

// ---------------------------------------------------------------------------
// fp16 GEMM v2: CTA 128x128, BK=64, **4 warps** (2m x 2n, warp tile 64x64),
// 3-stage cp.async pipeline, 2 CTAs/SM, 256-reg budget per thread so ptxas
// can pipeline fragment loads across ks slices (was hard-capped at 128).
// mode 0: C fp32 (Wo projection)
// mode 4: fused QKV. blockIdx.x<16 -> Q, 16..19 -> K, 20..23 -> V
// ---------------------------------------------------------------------------
#define A_ST 72
#define B_ST 136
#define A_SZ (128 * A_ST)
#define B_SZ (64 * B_ST)
#define GSMEM (3 * (A_SZ + B_SZ) * 2)

__global__ __launch_bounds__(128, 2) void gemm_f16(
    const __half* __restrict__ A, const __half* __restrict__ B0,
    const __half* __restrict__ B1, const __half* __restrict__ B2,
    float* __restrict__ C, int K, int mode)
{
    extern __shared__ __half smem[];
    __half* As = smem;
    __half* Bs = smem + 3 * A_SZ;

    const int tid = threadIdx.x, lane = tid & 31, wid = tid >> 5;
    const int wm = wid & 1, wn = wid >> 1;       // 2x2 warp grid, 64x64 tiles
    const int g = lane >> 2, t = lane & 3;
    const int m0 = blockIdx.y * 128;
    int n0 = blockIdx.x * 128;
    const __half* Bm = B0;
    int Nb = DM;
    int vmode = mode;
    if (mode == 4) {
        if (blockIdx.x < 16) {
            vmode = 1;
        } else if (blockIdx.x < 20) {
            Bm = B1; Nb = 512; n0 = (blockIdx.x - 16) * 128; vmode = 2;
        } else {
            Bm = B2; Nb = 512; n0 = (blockIdx.x - 20) * 128; vmode = 3;
        }
    }

    const uint32_t sA = smem_u32(As), sB = smem_u32(Bs);
    const int niter = K >> 6;

    float acc[4][8][4];
#pragma unroll
    for (int mf = 0; mf < 4; mf++)
#pragma unroll
        for (int nt = 0; nt < 8; nt++)
#pragma unroll
            for (int r = 0; r < 4; r++) acc[mf][nt][r] = 0.f;

    auto issue = [&](int it) {
        if (it >= niter) return;
        int kt = it << 6;
        int st = it % 3;
#pragma unroll
        for (int u = 0; u < 8; u++) {          // A: 128 rows x 64 cols
            int c = tid + 128 * u;
            int r = c >> 3, q = c & 7;
            cp16(sA + (st * A_SZ + r * A_ST + q * 8) * 2,
                 &A[(size_t)(m0 + r) * K + kt + q * 8]);
        }
#pragma unroll
        for (int u = 0; u < 8; u++) {          // B: 64 rows x 128 cols
            int c = tid + 128 * u;
            int r = c >> 4, q = c & 15;
            cp16(sB + (st * B_SZ + r * B_ST + q * 8) * 2,
                 &Bm[(size_t)(kt + r) * Nb + n0 + q * 8]);
        }
    };

    issue(0); CP_COMMIT();
    issue(1); CP_COMMIT();

    for (int i = 0; i < niter; i++) {
        CP_WAIT(1);
        __syncthreads();
        const int st = i % 3;
        const uint32_t ab = sA + st * A_SZ * 2;
        const uint32_t bb = sB + st * B_SZ * 2;
#pragma unroll
        for (int ks = 0; ks < 4; ks++) {
            const int kb = ks * 16;
            uint32_t af[4][4], bf[8][2];
#pragma unroll
            for (int mf = 0; mf < 4; mf++)
                ldmx4(af[mf], ab + ((wm * 64 + mf * 16 + (lane & 15)) * A_ST +
                                    kb + (lane >> 4) * 8) * 2);
#pragma unroll
            for (int p = 0; p < 4; p++) {
                uint32_t r[4];
                ldmx4t(r, bb + ((kb + (lane & 15)) * B_ST +
                                wn * 64 + p * 16 + (lane >> 4) * 8) * 2);
                bf[2 * p][0] = r[0]; bf[2 * p][1] = r[1];
                bf[2 * p + 1][0] = r[2]; bf[2 * p + 1][1] = r[3];
            }
#pragma unroll
            for (int mf = 0; mf < 4; mf++)
#pragma unroll
                for (int nt = 0; nt < 8; nt++)
                    mma_f16(acc[mf][nt], af[mf], bf[nt]);
        }
        issue(i + 2);
        CP_COMMIT();
    }

    if (mode == 0) {
#pragma unroll
        for (int mf = 0; mf < 4; mf++) {
            int r = m0 + wm * 64 + mf * 16 + g;
#pragma unroll
            for (int nt = 0; nt < 8; nt++) {
                int col = n0 + wn * 64 + nt * 8 + t * 2;
                *(float2*)&C[(size_t)r * DM + col] =
                    make_float2(acc[mf][nt][0], acc[mf][nt][1]);
                *(float2*)&C[(size_t)(r + 8) * DM + col] =
                    make_float2(acc[mf][nt][2], acc[mf][nt][3]);
            }
        }
        return;
    }

#pragma unroll
    for (int mf = 0; mf < 4; mf++) {
#pragma unroll
        for (int hh = 0; hh < 2; hh++) {
            int row = m0 + wm * 64 + mf * 16 + g + hh * 8;
            int b = row >> 11;
            int s = row & (SEQ - 1);
#pragma unroll
            for (int nt = 0; nt < 8; nt++) {
                int col = n0 + wn * 64 + nt * 8 + t * 2;
                float v0 = acc[mf][nt][hh * 2 + 0];
                float v1 = acc[mf][nt][hh * 2 + 1];
                int d0 = col & 63;
                if (vmode != 3) {
                    int j0 = d0 & 31, j1 = (d0 + 1) & 31;
                    float2 cs0 = *(const float2*)&g_rope[((size_t)s * 32 + j0) * 2];
                    float2 cs1 = *(const float2*)&g_rope[((size_t)s * 32 + j1) * 2];
                    float o0 = v0 * cs0.x - v1 * cs0.y;
                    float o1 = v1 * cs1.x + v0 * cs1.y;
                    if (vmode == 1) { o0 *= QSCALE; o1 *= QSCALE; }
                    v0 = o0; v1 = o1;
                }
                int h = col >> 6;
                __half2 hv = __floats2half2_rn(v0, v1);
                if (vmode == 1)
                    *(__half2*)&g_q[(((size_t)b * NUM_HEADS + h) * SEQ + s) * HD + d0] = hv;
                else if (vmode == 2)
                    *(__half2*)&g_k[(((size_t)b * NUM_KV + h) * SEQ + s) * HD + d0] = hv;
                else
                    *(__half2*)&g_v[(((size_t)b * NUM_KV + h) * SEQ + s) * HD + d0] = hv;
            }
        }
    }
}

// ---------------------------------------------------------------------------
// fp16 mma flash attention v2 (unchanged from round 9).
// ---------------------------------------------------------------------------
#define FSTR 72
#define FA_SMEM ((128 + 4 * 64) * FSTR * 2)

__global__ __launch_bounds__(128) void fa_f16()
{
    extern __shared__ __half sm[];
    __half* q_s = sm;                        // [128][72]
    __half* k_s = sm + 128 * FSTR;           // [2][64][72]
    __half* v_s = sm + 128 * FSTR + 2 * 64 * FSTR;

    const int tid = threadIdx.x, lane = tid & 31, w = tid >> 5;
    const int g = lane >> 2, t = lane & 3;
    const int qs = ((int)gridDim.x - 1 - (int)blockIdx.x) * 128;
    const int h = blockIdx.y, b = blockIdx.z;
    const int kvh = h >> 2;

    const __half* qg = &g_q[(((size_t)b * NUM_HEADS + h) * SEQ + qs) * HD];
    const __half* kg = &g_k[(((size_t)b * NUM_KV + kvh) * SEQ) * HD];
    const __half* vg = &g_v[(((size_t)b * NUM_KV + kvh) * SEQ) * HD];

    const uint32_t sq = smem_u32(q_s), sk = smem_u32(k_s), sv = smem_u32(v_s);

#pragma unroll
    for (int u = 0; u < 8; u++) {
        int c = tid + 128 * u;
        int r = c >> 3, q = c & 7;
        cp16(sq + (r * FSTR + q * 8) * 2, qg + (size_t)r * 64 + q * 8);
    }
    auto issue_kv = [&](int it) {
        int st = it & 1, koff = it * 64;
#pragma unroll
        for (int u = 0; u < 4; u++) {
            int c = tid + 128 * u;
            int r = c >> 3, q = c & 7;
            cp16(sk + (st * 64 * FSTR + r * FSTR + q * 8) * 2,
                 kg + (size_t)(koff + r) * 64 + q * 8);
            cp16(sv + (st * 64 * FSTR + r * FSTR + q * 8) * 2,
                 vg + (size_t)(koff + r) * 64 + q * 8);
        }
    };
    const int ntiles = qs / 64 + 2;
    issue_kv(0); CP_COMMIT();
    if (ntiles > 1) issue_kv(1);
    CP_COMMIT();

    float o[2][8][4];
#pragma unroll
    for (int mf = 0; mf < 2; mf++)
#pragma unroll
        for (int p = 0; p < 8; p++)
#pragma unroll
            for (int r = 0; r < 4; r++) o[mf][p][r] = 0.f;
    float mr[2][2], lr[2][2];
#pragma unroll
    for (int mf = 0; mf < 2; mf++) {
        mr[mf][0] = mr[mf][1] = -1e30f;
        lr[mf][0] = lr[mf][1] = 0.f;
    }
    uint32_t qf[2][4][4];

    for (int it = 0; it < ntiles; it++) {
        CP_WAIT(1);
        __syncthreads();
        if (it == 0) {
#pragma unroll
            for (int mf = 0; mf < 2; mf++)
#pragma unroll
                for (int kc = 0; kc < 4; kc++)
                    ldmx4(qf[mf][kc],
                          sq + ((w * 32 + mf * 16 + (lane & 15)) * FSTR +
                                kc * 16 + (lane >> 4) * 8) * 2);
        }
        const uint32_t kb = sk + ((it & 1) * 64 * FSTR) * 2;
        const uint32_t vb = sv + ((it & 1) * 64 * FSTR) * 2;

        float s[2][8][4];
#pragma unroll
        for (int mf = 0; mf < 2; mf++)
#pragma unroll
            for (int p = 0; p < 8; p++)
#pragma unroll
                for (int r = 0; r < 4; r++) s[mf][p][r] = 0.f;
#pragma unroll
        for (int kc = 0; kc < 4; kc++) {
#pragma unroll
            for (int p = 0; p < 4; p++) {
                uint32_t r[4];
                ldmx4(r, kb + ((p * 16 + (lane & 7) + ((lane >> 4) & 1) * 8) * FSTR +
                               kc * 16 + ((lane >> 3) & 1) * 8) * 2);
#pragma unroll
                for (int mf = 0; mf < 2; mf++) {
                    mma_f16(s[mf][2 * p], qf[mf][kc], r);
                    mma_f16(s[mf][2 * p + 1], qf[mf][kc], r + 2);
                }
            }
        }

        const int kt = it * 64;
        uint32_t pf[2][4][4];
#pragma unroll
        for (int mf = 0; mf < 2; mf++) {
            const int rowg = qs + w * 32 + mf * 16 + g;
            if (kt + 63 > qs + w * 32 + mf * 16) {
#pragma unroll
                for (int p = 0; p < 8; p++) {
                    int col = kt + p * 8 + 2 * t;
                    if (col > rowg)     s[mf][p][0] = -1e30f;
                    if (col + 1 > rowg) s[mf][p][1] = -1e30f;
                    if (col > rowg + 8)     s[mf][p][2] = -1e30f;
                    if (col + 1 > rowg + 8) s[mf][p][3] = -1e30f;
                }
            }

            float mx0 = -1e30f, mx1 = -1e30f;
#pragma unroll
            for (int p = 0; p < 8; p++) {
                mx0 = fmaxf(mx0, fmaxf(s[mf][p][0], s[mf][p][1]));
                mx1 = fmaxf(mx1, fmaxf(s[mf][p][2], s[mf][p][3]));
            }
            mx0 = fmaxf(mx0, __shfl_xor_sync(0xffffffffu, mx0, 1));
            mx0 = fmaxf(mx0, __shfl_xor_sync(0xffffffffu, mx0, 2));
            mx1 = fmaxf(mx1, __shfl_xor_sync(0xffffffffu, mx1, 1));
            mx1 = fmaxf(mx1, __shfl_xor_sync(0xffffffffu, mx1, 2));
            float mn0 = fmaxf(mr[mf][0], mx0), mn1 = fmaxf(mr[mf][1], mx1);
            float a0 = ex2(mr[mf][0] - mn0), a1 = ex2(mr[mf][1] - mn1);
            mr[mf][0] = mn0; mr[mf][1] = mn1;

            __half2 acc0 = __floats2half2_rn(0.f, 0.f);
            __half2 acc1 = acc0;
#pragma unroll
            for (int p = 0; p < 8; p++) {
                uint32_t e0 = ex2h2(packh2(s[mf][p][0] - mn0, s[mf][p][1] - mn0));
                uint32_t e1 = ex2h2(packh2(s[mf][p][2] - mn1, s[mf][p][3] - mn1));
                acc0 = __hadd2(acc0, *reinterpret_cast<__half2*>(&e0));
                acc1 = __hadd2(acc1, *reinterpret_cast<__half2*>(&e1));
                int kc = p >> 1;
                if ((p & 1) == 0) { pf[mf][kc][0] = e0; pf[mf][kc][1] = e1; }
                else              { pf[mf][kc][2] = e0; pf[mf][kc][3] = e1; }
            }
            float ps0 = __low2float(acc0) + __high2float(acc0);
            float ps1 = __low2float(acc1) + __high2float(acc1);
            ps0 += __shfl_xor_sync(0xffffffffu, ps0, 1);
            ps0 += __shfl_xor_sync(0xffffffffu, ps0, 2);
            ps1 += __shfl_xor_sync(0xffffffffu, ps1, 1);
            ps1 += __shfl_xor_sync(0xffffffffu, ps1, 2);
            lr[mf][0] = lr[mf][0] * a0 + ps0;
            lr[mf][1] = lr[mf][1] * a1 + ps1;
#pragma unroll
            for (int p = 0; p < 8; p++) {
                o[mf][p][0] *= a0; o[mf][p][1] *= a0;
                o[mf][p][2] *= a1; o[mf][p][3] *= a1;
            }
        }

#pragma unroll
        for (int kc = 0; kc < 4; kc++) {
#pragma unroll
            for (int p = 0; p < 4; p++) {
                uint32_t r[4];
                ldmx4t(r, vb + ((kc * 16 + (lane & 15)) * FSTR +
                                p * 16 + ((lane >> 4) & 1) * 8) * 2);
#pragma unroll
                for (int mf = 0; mf < 2; mf++) {
                    mma_f16(o[mf][2 * p], pf[mf][kc], r);
                    mma_f16(o[mf][2 * p + 1], pf[mf][kc], r + 2);
                }
            }
        }

        __syncthreads();
        if (it + 2 < ntiles) issue_kv(it + 2);
        CP_COMMIT();
    }

#pragma unroll
    for (int mf = 0; mf < 2; mf++) {
        float inv0 = 1.f / lr[mf][0], inv1 = 1.f / lr[mf][1];
        __half* og = &g_ao[((size_t)(b * SEQ + qs + w * 32 + mf * 16)) * DM + h * HD];
#pragma unroll
        for (int p = 0; p < 8; p++) {
            int col = p * 8 + 2 * t;
            *(__half2*)&og[(size_t)g * DM + col] =
                __floats2half2_rn(o[mf][p][0] * inv0, o[mf][p][1] * inv0);
            *(__half2*)&og[(size_t)(g + 8) * DM + col] =
                __floats2half2_rn(o[mf][p][2] * inv1, o[mf][p][3] * inv1);
        }
    }
}

// ---------------------------------------------------------------------------

extern "C" void kernel_launch(void* const* d_in, const int* in_sizes, int n_in,
                              void* d_out, int out_size)
{
    const float* x  = (const float*)d_in[0];
    const float* Wq = (const float*)d_in[2];
    const float* Wk = (const float*)d_in[3];
    const float* Wv = (const float*)d_in[4];
    const float* Wo = (const float*)d_in[5];
    float* out = (float*)d_out;

    void *xh, *wq, *wk, *wv, *wo, *ao;
    cudaGetSymbolAddress(&xh, g_xh);
    cudaGetSymbolAddress(&wq, g_wq);
    cudaGetSymbolAddress(&wk, g_wk);
    cudaGetSymbolAddress(&wv, g_wv);
    cudaGetSymbolAddress(&wo, g_wo);
    cudaGetSymbolAddress(&ao, g_ao);

    cudaFuncSetAttribute(gemm_f16, cudaFuncAttributeMaxDynamicSharedMemorySize, GSMEM);
    cudaFuncSetAttribute(fa_f16, cudaFuncAttributeMaxDynamicSharedMemorySize, FA_SMEM);

    // fused prologue: all conversions + rope table (one launch)
    prep<<<18688, 256>>>((const float4*)x, (const float4*)Wq, (const float4*)Wk,
                         (const float4*)Wv, (const float4*)Wo);

    // fused Q+K+V projections (RoPE on Q/K, scale folded into Q)
    gemm_f16<<<dim3(24, MTOT / 128), 128, GSMEM>>>(
        (const __half*)xh, (const __half*)wq, (const __half*)wk,
        (const __half*)wv, nullptr, DM, 4);

    // flash attention (4 warps x 32 rows, heavy-first)
    fa_f16<<<dim3(SEQ / 128, NUM_HEADS, B_DIM), 128, FA_SMEM>>>();

    // output projection
    gemm_f16<<<dim3(DM / 128, MTOT / 128), 128, GSMEM>>>(
        (const __half*)ao, (const __half*)wo, nullptr, nullptr, out, DM, 0);
}

// round 11
// speedup vs baseline: 1.0614x; 1.0614x over previous
#include <cuda_runtime.h>
#include <cuda_fp16.h>
#include <math.h>
#include <stdint.h>

#define B_DIM 2
#define NUM_HEADS 32
#define NUM_KV 8
#define SEQ 2048
#define DM 2048
#define HD 64
#define MTOT (B_DIM * SEQ)

// fp16 scratch (allocation-free device globals)
__device__ __half g_xh[(size_t)MTOT * DM];
__device__ __half g_wq[(size_t)DM * DM];
__device__ __half g_wk[(size_t)DM * 512];
__device__ __half g_wv[(size_t)DM * 512];
__device__ __half g_wo[(size_t)DM * DM];
__device__ __half g_q[(size_t)B_DIM * NUM_HEADS * SEQ * HD];
__device__ __half g_k[(size_t)B_DIM * NUM_KV * SEQ * HD];
__device__ __half g_v[(size_t)B_DIM * NUM_KV * SEQ * HD];
__device__ __half g_ao[(size_t)MTOT * DM];
__device__ float  g_rope[SEQ * 32 * 2];

// softmax scale folded into Q at projection time: 1/sqrt(64) * log2(e)
#define QSCALE 0.1803368801111204f

// ---------------------------------------------------------------------------
// Fused prologue: all fp32->fp16 conversions + RoPE table in ONE launch.
// ---------------------------------------------------------------------------
__global__ void prep(const float4* __restrict__ x, const float4* __restrict__ wq,
                     const float4* __restrict__ wk, const float4* __restrict__ wv,
                     const float4* __restrict__ wo)
{
    const int b = blockIdx.x, tid = threadIdx.x;
    const float4* src;
    __half* dst;
    int base;
    if (b < 8192)       { src = x;  dst = g_xh; base = 0; }
    else if (b < 12288) { src = wq; dst = g_wq; base = 8192; }
    else if (b < 13312) { src = wk; dst = g_wk; base = 12288; }
    else if (b < 14336) { src = wv; dst = g_wv; base = 13312; }
    else if (b < 18432) { src = wo; dst = g_wo; base = 14336; }
    else {
        int i = (b - 18432) * 256 + tid;
        int s = i >> 5, j = i & 31;
        float inv = expf(-(float)j * 0.28782313662425572f);
        float sv, cv;
        sincosf((float)s * inv, &sv, &cv);
        g_rope[(size_t)i * 2 + 0] = cv;
        g_rope[(size_t)i * 2 + 1] = sv;
        return;
    }
    size_t i = (size_t)(b - base) * 256 + tid;
    float4 v = src[i];
    __half2* d = (__half2*)(dst + i * 4);
    d[0] = __floats2half2_rn(v.x, v.y);
    d[1] = __floats2half2_rn(v.z, v.w);
}

// ---------------------------------------------------------------------------
// Helpers
// ---------------------------------------------------------------------------
__device__ __forceinline__ uint32_t smem_u32(const void* p)
{
    return (uint32_t)__cvta_generic_to_shared(p);
}
__device__ __forceinline__ void ldmx4(uint32_t* r, uint32_t a)
{
    asm volatile("ldmatrix.sync.aligned.m8n8.x4.shared.b16 {%0,%1,%2,%3}, [%4];"
                 : "=r"(r[0]), "=r"(r[1]), "=r"(r[2]), "=r"(r[3]) : "r"(a));
}
__device__ __forceinline__ void ldmx4t(uint32_t* r, uint32_t a)
{
    asm volatile("ldmatrix.sync.aligned.m8n8.x4.trans.shared.b16 {%0,%1,%2,%3}, [%4];"
                 : "=r"(r[0]), "=r"(r[1]), "=r"(r[2]), "=r"(r[3]) : "r"(a));
}
__device__ __forceinline__ void mma_f16(float* c, const uint32_t* a, const uint32_t* b)
{
    asm volatile(
        "mma.sync.aligned.m16n8k16.row.col.f32.f16.f16.f32 "
        "{%0,%1,%2,%3}, {%4,%5,%6,%7}, {%8,%9}, {%0,%1,%2,%3};"
        : "+f"(c[0]), "+f"(c[1]), "+f"(c[2]), "+f"(c[3])
        : "r"(a[0]), "r"(a[1]), "r"(a[2]), "r"(a[3]), "r"(b[0]), "r"(b[1]));
}
__device__ __forceinline__ void cp16(uint32_t saddr, const void* g)
{
    asm volatile("cp.async.cg.shared.global [%0], [%1], 16;" :: "r"(saddr), "l"(g));
}
#define CP_COMMIT() asm volatile("cp.async.commit_group;")
#define CP_WAIT(n)  asm volatile("cp.async.wait_group %0;" :: "n"(n))

__device__ __forceinline__ float ex2(float x)
{
    float r;
    asm("ex2.approx.ftz.f32 %0, %1;" : "=f"(r) : "f"(x));
    return r;
}
__device__ __forceinline__ uint32_t ex2h2(uint32_t x)
{
    uint32_t r;
    asm("ex2.approx.f16x2 %0, %1;" : "=r"(r) : "r"(x));
    return r;
}
__device__ __forceinline__ uint32_t packh2(float lo, float hi)
{
    __half2 h = __floats2half2_rn(lo, hi);
    return *reinterpret_cast<uint32_t*>(&h);
}

// ---------------------------------------------------------------------------
// fp16 GEMM (reverted to round-8 champion): CTA 128x128, BK=64, 8 warps
// (4m x 2n, warp tile 32x64), 3-stage cp.async pipeline, 2 CTAs/SM.
// mode 0: C fp32 (Wo projection)
// mode 4: fused QKV. blockIdx.x<16 -> Q, 16..19 -> K, 20..23 -> V
// ---------------------------------------------------------------------------
#define A_ST 72
#define B_ST 136
#define A_SZ (128 * A_ST)
#define B_SZ (64 * B_ST)
#define GSMEM (3 * (A_SZ + B_SZ) * 2)

__global__ __launch_bounds__(256, 2) void gemm_f16(
    const __half* __restrict__ A, const __half* __restrict__ B0,
    const __half* __restrict__ B1, const __half* __restrict__ B2,
    float* __restrict__ C, int K, int mode)
{
    extern __shared__ __half smem[];
    __half* As = smem;
    __half* Bs = smem + 3 * A_SZ;

    const int tid = threadIdx.x, lane = tid & 31, wid = tid >> 5;
    const int wm = wid & 3, wn = wid >> 2;
    const int g = lane >> 2, t = lane & 3;
    const int m0 = blockIdx.y * 128;
    int n0 = blockIdx.x * 128;
    const __half* Bm = B0;
    int Nb = DM;
    int vmode = mode;
    if (mode == 4) {
        if (blockIdx.x < 16) {
            vmode = 1;
        } else if (blockIdx.x < 20) {
            Bm = B1; Nb = 512; n0 = (blockIdx.x - 16) * 128; vmode = 2;
        } else {
            Bm = B2; Nb = 512; n0 = (blockIdx.x - 20) * 128; vmode = 3;
        }
    }

    const uint32_t sA = smem_u32(As), sB = smem_u32(Bs);
    const int niter = K >> 6;

    float acc[2][8][4];
#pragma unroll
    for (int mf = 0; mf < 2; mf++)
#pragma unroll
        for (int nt = 0; nt < 8; nt++)
#pragma unroll
            for (int r = 0; r < 4; r++) acc[mf][nt][r] = 0.f;

    auto issue = [&](int it) {
        if (it >= niter) return;
        int kt = it << 6;
        int st = it % 3;
#pragma unroll
        for (int u = 0; u < 4; u++) {
            int c = tid + 256 * u;
            int r = c >> 3, q = c & 7;
            cp16(sA + (st * A_SZ + r * A_ST + q * 8) * 2,
                 &A[(size_t)(m0 + r) * K + kt + q * 8]);
        }
#pragma unroll
        for (int u = 0; u < 4; u++) {
            int c = tid + 256 * u;
            int r = c >> 4, q = c & 15;
            cp16(sB + (st * B_SZ + r * B_ST + q * 8) * 2,
                 &Bm[(size_t)(kt + r) * Nb + n0 + q * 8]);
        }
    };

    issue(0); CP_COMMIT();
    issue(1); CP_COMMIT();

    for (int i = 0; i < niter; i++) {
        CP_WAIT(1);
        __syncthreads();
        const int st = i % 3;
        const uint32_t ab = sA + st * A_SZ * 2;
        const uint32_t bb = sB + st * B_SZ * 2;
#pragma unroll
        for (int ks = 0; ks < 4; ks++) {
            const int kb = ks * 16;
            uint32_t af[2][4], bf[8][2];
#pragma unroll
            for (int mf = 0; mf < 2; mf++)
                ldmx4(af[mf], ab + ((wm * 32 + mf * 16 + (lane & 15)) * A_ST +
                                    kb + (lane >> 4) * 8) * 2);
#pragma unroll
            for (int p = 0; p < 4; p++) {
                uint32_t r[4];
                ldmx4t(r, bb + ((kb + (lane & 15)) * B_ST +
                                wn * 64 + p * 16 + (lane >> 4) * 8) * 2);
                bf[2 * p][0] = r[0]; bf[2 * p][1] = r[1];
                bf[2 * p + 1][0] = r[2]; bf[2 * p + 1][1] = r[3];
            }
#pragma unroll
            for (int mf = 0; mf < 2; mf++)
#pragma unroll
                for (int nt = 0; nt < 8; nt++)
                    mma_f16(acc[mf][nt], af[mf], bf[nt]);
        }
        issue(i + 2);
        CP_COMMIT();
    }

    if (mode == 0) {
#pragma unroll
        for (int mf = 0; mf < 2; mf++) {
            int r = m0 + wm * 32 + mf * 16 + g;
#pragma unroll
            for (int nt = 0; nt < 8; nt++) {
                int col = n0 + wn * 64 + nt * 8 + t * 2;
                *(float2*)&C[(size_t)r * DM + col] =
                    make_float2(acc[mf][nt][0], acc[mf][nt][1]);
                *(float2*)&C[(size_t)(r + 8) * DM + col] =
                    make_float2(acc[mf][nt][2], acc[mf][nt][3]);
            }
        }
        return;
    }

#pragma unroll
    for (int mf = 0; mf < 2; mf++) {
#pragma unroll
        for (int hh = 0; hh < 2; hh++) {
            int row = m0 + wm * 32 + mf * 16 + g + hh * 8;
            int b = row >> 11;
            int s = row & (SEQ - 1);
#pragma unroll
            for (int nt = 0; nt < 8; nt++) {
                int col = n0 + wn * 64 + nt * 8 + t * 2;
                float v0 = acc[mf][nt][hh * 2 + 0];
                float v1 = acc[mf][nt][hh * 2 + 1];
                int d0 = col & 63;
                if (vmode != 3) {
                    int j0 = d0 & 31, j1 = (d0 + 1) & 31;
                    float2 cs0 = *(const float2*)&g_rope[((size_t)s * 32 + j0) * 2];
                    float2 cs1 = *(const float2*)&g_rope[((size_t)s * 32 + j1) * 2];
                    float o0 = v0 * cs0.x - v1 * cs0.y;
                    float o1 = v1 * cs1.x + v0 * cs1.y;
                    if (vmode == 1) { o0 *= QSCALE; o1 *= QSCALE; }
                    v0 = o0; v1 = o1;
                }
                int h = col >> 6;
                __half2 hv = __floats2half2_rn(v0, v1);
                if (vmode == 1)
                    *(__half2*)&g_q[(((size_t)b * NUM_HEADS + h) * SEQ + s) * HD + d0] = hv;
                else if (vmode == 2)
                    *(__half2*)&g_k[(((size_t)b * NUM_KV + h) * SEQ + s) * HD + d0] = hv;
                else
                    *(__half2*)&g_v[(((size_t)b * NUM_KV + h) * SEQ + s) * HD + d0] = hv;
            }
        }
    }
}

// ---------------------------------------------------------------------------
// fp16 mma flash attention: 8 warps x 16 Q rows (low per-thread state ~96 regs)
// FORCED to 2 CTAs/SM via launch_bounds(256,2) -> 16 warps/SM (4 per SMSP),
// so tensor/MUFU/shuffle phases of different warps overlap.
// ---------------------------------------------------------------------------
#define FSTR 72
#define FA_SMEM ((128 + 4 * 64) * FSTR * 2)

__global__ __launch_bounds__(256, 2) void fa_f16()
{
    extern __shared__ __half sm[];
    __half* q_s = sm;                        // [128][72]
    __half* k_s = sm + 128 * FSTR;           // [2][64][72]
    __half* v_s = sm + 128 * FSTR + 2 * 64 * FSTR;

    const int tid = threadIdx.x, lane = tid & 31, w = tid >> 5;
    const int g = lane >> 2, t = lane & 3;
    const int qs = ((int)gridDim.x - 1 - (int)blockIdx.x) * 128;  // heavy first
    const int h = blockIdx.y, b = blockIdx.z;
    const int kvh = h >> 2;

    const __half* qg = &g_q[(((size_t)b * NUM_HEADS + h) * SEQ + qs) * HD];
    const __half* kg = &g_k[(((size_t)b * NUM_KV + kvh) * SEQ) * HD];
    const __half* vg = &g_v[(((size_t)b * NUM_KV + kvh) * SEQ) * HD];

    const uint32_t sq = smem_u32(q_s), sk = smem_u32(k_s), sv = smem_u32(v_s);

#pragma unroll
    for (int u = 0; u < 4; u++) {
        int c = tid + 256 * u;
        int r = c >> 3, q = c & 7;
        cp16(sq + (r * FSTR + q * 8) * 2, qg + (size_t)r * 64 + q * 8);
    }
    auto issue_kv = [&](int it) {
        int st = it & 1, koff = it * 64;
#pragma unroll
        for (int u = 0; u < 2; u++) {
            int c = tid + 256 * u;
            int r = c >> 3, q = c & 7;
            cp16(sk + (st * 64 * FSTR + r * FSTR + q * 8) * 2,
                 kg + (size_t)(koff + r) * 64 + q * 8);
            cp16(sv + (st * 64 * FSTR + r * FSTR + q * 8) * 2,
                 vg + (size_t)(koff + r) * 64 + q * 8);
        }
    };
    const int ntiles = qs / 64 + 2;
    issue_kv(0); CP_COMMIT();
    if (ntiles > 1) issue_kv(1);
    CP_COMMIT();

    float o[8][4];
#pragma unroll
    for (int p = 0; p < 8; p++)
#pragma unroll
        for (int r = 0; r < 4; r++) o[p][r] = 0.f;
    float m0r = -1e30f, m1r = -1e30f, l0 = 0.f, l1 = 0.f;
    uint32_t qf[4][4];

    for (int it = 0; it < ntiles; it++) {
        CP_WAIT(1);
        __syncthreads();
        if (it == 0) {
#pragma unroll
            for (int kc = 0; kc < 4; kc++)
                ldmx4(qf[kc], sq + ((w * 16 + (lane & 15)) * FSTR +
                                    kc * 16 + (lane >> 4) * 8) * 2);
        }
        const uint32_t kb = sk + ((it & 1) * 64 * FSTR) * 2;
        const uint32_t vb = sv + ((it & 1) * 64 * FSTR) * 2;

        // S = Q @ K^T (scale pre-folded into Q)
        float s[8][4];
#pragma unroll
        for (int p = 0; p < 8; p++)
#pragma unroll
            for (int r = 0; r < 4; r++) s[p][r] = 0.f;
#pragma unroll
        for (int kc = 0; kc < 4; kc++) {
#pragma unroll
            for (int p = 0; p < 4; p++) {
                uint32_t r[4];
                ldmx4(r, kb + ((p * 16 + (lane & 7) + ((lane >> 4) & 1) * 8) * FSTR +
                               kc * 16 + ((lane >> 3) & 1) * 8) * 2);
                mma_f16(s[2 * p], qf[kc], r);
                mma_f16(s[2 * p + 1], qf[kc], r + 2);
            }
        }

        // causal mask on boundary tiles
        const int kt = it * 64;
        const int rowg = qs + w * 16 + g;
        if (kt + 63 > qs + w * 16) {
#pragma unroll
            for (int p = 0; p < 8; p++) {
                int col = kt + p * 8 + 2 * t;
                if (col > rowg)     s[p][0] = -1e30f;
                if (col + 1 > rowg) s[p][1] = -1e30f;
                if (col > rowg + 8)     s[p][2] = -1e30f;
                if (col + 1 > rowg + 8) s[p][3] = -1e30f;
            }
        }

        // online softmax (rows g and g+8), quad reductions
        float mx0 = -1e30f, mx1 = -1e30f;
#pragma unroll
        for (int p = 0; p < 8; p++) {
            mx0 = fmaxf(mx0, fmaxf(s[p][0], s[p][1]));
            mx1 = fmaxf(mx1, fmaxf(s[p][2], s[p][3]));
        }
        mx0 = fmaxf(mx0, __shfl_xor_sync(0xffffffffu, mx0, 1));
        mx0 = fmaxf(mx0, __shfl_xor_sync(0xffffffffu, mx0, 2));
        mx1 = fmaxf(mx1, __shfl_xor_sync(0xffffffffu, mx1, 1));
        mx1 = fmaxf(mx1, __shfl_xor_sync(0xffffffffu, mx1, 2));
        float mn0 = fmaxf(m0r, mx0), mn1 = fmaxf(m1r, mx1);
        float a0 = ex2(m0r - mn0), a1 = ex2(m1r - mn1);
        m0r = mn0; m1r = mn1;

        // exp in packed fp16 (same values feed the mma AND the row sum)
        __half2 acc0 = __floats2half2_rn(0.f, 0.f);
        __half2 acc1 = acc0;
        uint32_t pf[4][4];
#pragma unroll
        for (int p = 0; p < 8; p++) {
            uint32_t e0 = ex2h2(packh2(s[p][0] - mn0, s[p][1] - mn0));
            uint32_t e1 = ex2h2(packh2(s[p][2] - mn1, s[p][3] - mn1));
            acc0 = __hadd2(acc0, *reinterpret_cast<__half2*>(&e0));
            acc1 = __hadd2(acc1, *reinterpret_cast<__half2*>(&e1));
            int kc = p >> 1;
            if ((p & 1) == 0) { pf[kc][0] = e0; pf[kc][1] = e1; }
            else              { pf[kc][2] = e0; pf[kc][3] = e1; }
        }
        float ps0 = __low2float(acc0) + __high2float(acc0);
        float ps1 = __low2float(acc1) + __high2float(acc1);
        ps0 += __shfl_xor_sync(0xffffffffu, ps0, 1);
        ps0 += __shfl_xor_sync(0xffffffffu, ps0, 2);
        ps1 += __shfl_xor_sync(0xffffffffu, ps1, 1);
        ps1 += __shfl_xor_sync(0xffffffffu, ps1, 2);
        l0 = l0 * a0 + ps0;
        l1 = l1 * a1 + ps1;
#pragma unroll
        for (int p = 0; p < 8; p++) {
            o[p][0] *= a0; o[p][1] *= a0;
            o[p][2] *= a1; o[p][3] *= a1;
        }

        // O += P @ V
#pragma unroll
        for (int kc = 0; kc < 4; kc++) {
#pragma unroll
            for (int p = 0; p < 4; p++) {
                uint32_t r[4];
                ldmx4t(r, vb + ((kc * 16 + (lane & 15)) * FSTR +
                                p * 16 + ((lane >> 4) & 1) * 8) * 2);
                mma_f16(o[2 * p], pf[kc], r);
                mma_f16(o[2 * p + 1], pf[kc], r + 2);
            }
        }

        __syncthreads();
        if (it + 2 < ntiles) issue_kv(it + 2);
        CP_COMMIT();
    }

    // epilogue
    float inv0 = 1.f / l0, inv1 = 1.f / l1;
    __half* og = &g_ao[((size_t)(b * SEQ + qs + w * 16)) * DM + h * HD];
#pragma unroll
    for (int p = 0; p < 8; p++) {
        int col = p * 8 + 2 * t;
        *(__half2*)&og[(size_t)g * DM + col] =
            __floats2half2_rn(o[p][0] * inv0, o[p][1] * inv0);
        *(__half2*)&og[(size_t)(g + 8) * DM + col] =
            __floats2half2_rn(o[p][2] * inv1, o[p][3] * inv1);
    }
}

// ---------------------------------------------------------------------------

extern "C" void kernel_launch(void* const* d_in, const int* in_sizes, int n_in,
                              void* d_out, int out_size)
{
    const float* x  = (const float*)d_in[0];
    const float* Wq = (const float*)d_in[2];
    const float* Wk = (const float*)d_in[3];
    const float* Wv = (const float*)d_in[4];
    const float* Wo = (const float*)d_in[5];
    float* out = (float*)d_out;

    void *xh, *wq, *wk, *wv, *wo, *ao;
    cudaGetSymbolAddress(&xh, g_xh);
    cudaGetSymbolAddress(&wq, g_wq);
    cudaGetSymbolAddress(&wk, g_wk);
    cudaGetSymbolAddress(&wv, g_wv);
    cudaGetSymbolAddress(&wo, g_wo);
    cudaGetSymbolAddress(&ao, g_ao);

    cudaFuncSetAttribute(gemm_f16, cudaFuncAttributeMaxDynamicSharedMemorySize, GSMEM);
    cudaFuncSetAttribute(fa_f16, cudaFuncAttributeMaxDynamicSharedMemorySize, FA_SMEM);

    // fused prologue: all conversions + rope table (one launch)
    prep<<<18688, 256>>>((const float4*)x, (const float4*)Wq, (const float4*)Wk,
                         (const float4*)Wv, (const float4*)Wo);

    // fused Q+K+V projections (RoPE on Q/K, scale folded into Q)
    gemm_f16<<<dim3(24, MTOT / 128), 256, GSMEM>>>(
        (const __half*)xh, (const __half*)wq, (const __half*)wk,
        (const __half*)wv, nullptr, DM, 4);

    // flash attention (8 warps x 16 rows, 2 CTAs/SM forced, heavy-first)
    fa_f16<<<dim3(SEQ / 128, NUM_HEADS, B_DIM), 256, FA_SMEM>>>();

    // output projection
    gemm_f16<<<dim3(DM / 128, MTOT / 128), 256, GSMEM>>>(
        (const __half*)ao, (const __half*)wo, nullptr, nullptr, out, DM, 0);
}

// round 12
// speedup vs baseline: 1.0882x; 1.0253x over previous
#include <cuda_runtime.h>
#include <cuda_fp16.h>
#include <math.h>
#include <stdint.h>

#define B_DIM 2
#define NUM_HEADS 32
#define NUM_KV 8
#define SEQ 2048
#define DM 2048
#define HD 64
#define MTOT (B_DIM * SEQ)

// fp16 scratch (allocation-free device globals)
__device__ __half g_xh[(size_t)MTOT * DM];
__device__ __half g_wq[(size_t)DM * DM];
__device__ __half g_wk[(size_t)DM * 512];
__device__ __half g_wv[(size_t)DM * 512];
__device__ __half g_wo[(size_t)DM * DM];
__device__ __half g_q[(size_t)B_DIM * NUM_HEADS * SEQ * HD];
__device__ __half g_k[(size_t)B_DIM * NUM_KV * SEQ * HD];
__device__ __half g_v[(size_t)B_DIM * NUM_KV * SEQ * HD];
__device__ __half g_ao[(size_t)MTOT * DM];
__device__ float  g_rope[SEQ * 32 * 2];

// softmax scale folded into Q at projection time: 1/sqrt(64) * log2(e)
#define QSCALE 0.1803368801111204f

// ---------------------------------------------------------------------------
// Fused prologue: all fp32->fp16 conversions + RoPE table in ONE launch.
// ---------------------------------------------------------------------------
__global__ void prep(const float4* __restrict__ x, const float4* __restrict__ wq,
                     const float4* __restrict__ wk, const float4* __restrict__ wv,
                     const float4* __restrict__ wo)
{
    const int b = blockIdx.x, tid = threadIdx.x;
    const float4* src;
    __half* dst;
    int base;
    if (b < 8192)       { src = x;  dst = g_xh; base = 0; }
    else if (b < 12288) { src = wq; dst = g_wq; base = 8192; }
    else if (b < 13312) { src = wk; dst = g_wk; base = 12288; }
    else if (b < 14336) { src = wv; dst = g_wv; base = 13312; }
    else if (b < 18432) { src = wo; dst = g_wo; base = 14336; }
    else {
        int i = (b - 18432) * 256 + tid;
        int s = i >> 5, j = i & 31;
        float inv = expf(-(float)j * 0.28782313662425572f);
        float sv, cv;
        sincosf((float)s * inv, &sv, &cv);
        g_rope[(size_t)i * 2 + 0] = cv;
        g_rope[(size_t)i * 2 + 1] = sv;
        return;
    }
    size_t i = (size_t)(b - base) * 256 + tid;
    float4 v = src[i];
    __half2* d = (__half2*)(dst + i * 4);
    d[0] = __floats2half2_rn(v.x, v.y);
    d[1] = __floats2half2_rn(v.z, v.w);
}

// ---------------------------------------------------------------------------
// Helpers
// ---------------------------------------------------------------------------
__device__ __forceinline__ uint32_t smem_u32(const void* p)
{
    return (uint32_t)__cvta_generic_to_shared(p);
}
__device__ __forceinline__ void ldmx4(uint32_t* r, uint32_t a)
{
    asm volatile("ldmatrix.sync.aligned.m8n8.x4.shared.b16 {%0,%1,%2,%3}, [%4];"
                 : "=r"(r[0]), "=r"(r[1]), "=r"(r[2]), "=r"(r[3]) : "r"(a));
}
__device__ __forceinline__ void ldmx4t(uint32_t* r, uint32_t a)
{
    asm volatile("ldmatrix.sync.aligned.m8n8.x4.trans.shared.b16 {%0,%1,%2,%3}, [%4];"
                 : "=r"(r[0]), "=r"(r[1]), "=r"(r[2]), "=r"(r[3]) : "r"(a));
}
__device__ __forceinline__ void mma_f16(float* c, const uint32_t* a, const uint32_t* b)
{
    asm volatile(
        "mma.sync.aligned.m16n8k16.row.col.f32.f16.f16.f32 "
        "{%0,%1,%2,%3}, {%4,%5,%6,%7}, {%8,%9}, {%0,%1,%2,%3};"
        : "+f"(c[0]), "+f"(c[1]), "+f"(c[2]), "+f"(c[3])
        : "r"(a[0]), "r"(a[1]), "r"(a[2]), "r"(a[3]), "r"(b[0]), "r"(b[1]));
}
__device__ __forceinline__ void cp16(uint32_t saddr, const void* g)
{
    asm volatile("cp.async.cg.shared.global [%0], [%1], 16;" :: "r"(saddr), "l"(g));
}
#define CP_COMMIT() asm volatile("cp.async.commit_group;")
#define CP_WAIT(n)  asm volatile("cp.async.wait_group %0;" :: "n"(n))
#define BARG(id)    asm volatile("bar.sync %0, %1;" :: "r"(id), "r"(256) : "memory")

__device__ __forceinline__ float ex2(float x)
{
    float r;
    asm("ex2.approx.ftz.f32 %0, %1;" : "=f"(r) : "f"(x));
    return r;
}
__device__ __forceinline__ uint32_t ex2h2(uint32_t x)
{
    uint32_t r;
    asm("ex2.approx.f16x2 %0, %1;" : "=r"(r) : "r"(x));
    return r;
}
__device__ __forceinline__ uint32_t packh2(float lo, float hi)
{
    __half2 h = __floats2half2_rn(lo, hi);
    return *reinterpret_cast<uint32_t*>(&h);
}

// ---------------------------------------------------------------------------
// fp16 GEMM (champion config): CTA 128x128, BK=64, 8 warps (4m x 2n),
// 3-stage cp.async pipeline, 2 CTAs/SM.
// ---------------------------------------------------------------------------
#define A_ST 72
#define B_ST 136
#define A_SZ (128 * A_ST)
#define B_SZ (64 * B_ST)
#define GSMEM (3 * (A_SZ + B_SZ) * 2)

__global__ __launch_bounds__(256, 2) void gemm_f16(
    const __half* __restrict__ A, const __half* __restrict__ B0,
    const __half* __restrict__ B1, const __half* __restrict__ B2,
    float* __restrict__ C, int K, int mode)
{
    extern __shared__ __half smem[];
    __half* As = smem;
    __half* Bs = smem + 3 * A_SZ;

    const int tid = threadIdx.x, lane = tid & 31, wid = tid >> 5;
    const int wm = wid & 3, wn = wid >> 2;
    const int g = lane >> 2, t = lane & 3;
    const int m0 = blockIdx.y * 128;
    int n0 = blockIdx.x * 128;
    const __half* Bm = B0;
    int Nb = DM;
    int vmode = mode;
    if (mode == 4) {
        if (blockIdx.x < 16) {
            vmode = 1;
        } else if (blockIdx.x < 20) {
            Bm = B1; Nb = 512; n0 = (blockIdx.x - 16) * 128; vmode = 2;
        } else {
            Bm = B2; Nb = 512; n0 = (blockIdx.x - 20) * 128; vmode = 3;
        }
    }

    const uint32_t sA = smem_u32(As), sB = smem_u32(Bs);
    const int niter = K >> 6;

    float acc[2][8][4];
#pragma unroll
    for (int mf = 0; mf < 2; mf++)
#pragma unroll
        for (int nt = 0; nt < 8; nt++)
#pragma unroll
            for (int r = 0; r < 4; r++) acc[mf][nt][r] = 0.f;

    auto issue = [&](int it) {
        if (it >= niter) return;
        int kt = it << 6;
        int st = it % 3;
#pragma unroll
        for (int u = 0; u < 4; u++) {
            int c = tid + 256 * u;
            int r = c >> 3, q = c & 7;
            cp16(sA + (st * A_SZ + r * A_ST + q * 8) * 2,
                 &A[(size_t)(m0 + r) * K + kt + q * 8]);
        }
#pragma unroll
        for (int u = 0; u < 4; u++) {
            int c = tid + 256 * u;
            int r = c >> 4, q = c & 15;
            cp16(sB + (st * B_SZ + r * B_ST + q * 8) * 2,
                 &Bm[(size_t)(kt + r) * Nb + n0 + q * 8]);
        }
    };

    issue(0); CP_COMMIT();
    issue(1); CP_COMMIT();

    for (int i = 0; i < niter; i++) {
        CP_WAIT(1);
        __syncthreads();
        const int st = i % 3;
        const uint32_t ab = sA + st * A_SZ * 2;
        const uint32_t bb = sB + st * B_SZ * 2;
#pragma unroll
        for (int ks = 0; ks < 4; ks++) {
            const int kb = ks * 16;
            uint32_t af[2][4], bf[8][2];
#pragma unroll
            for (int mf = 0; mf < 2; mf++)
                ldmx4(af[mf], ab + ((wm * 32 + mf * 16 + (lane & 15)) * A_ST +
                                    kb + (lane >> 4) * 8) * 2);
#pragma unroll
            for (int p = 0; p < 4; p++) {
                uint32_t r[4];
                ldmx4t(r, bb + ((kb + (lane & 15)) * B_ST +
                                wn * 64 + p * 16 + (lane >> 4) * 8) * 2);
                bf[2 * p][0] = r[0]; bf[2 * p][1] = r[1];
                bf[2 * p + 1][0] = r[2]; bf[2 * p + 1][1] = r[3];
            }
#pragma unroll
            for (int mf = 0; mf < 2; mf++)
#pragma unroll
                for (int nt = 0; nt < 8; nt++)
                    mma_f16(acc[mf][nt], af[mf], bf[nt]);
        }
        issue(i + 2);
        CP_COMMIT();
    }

    if (mode == 0) {
#pragma unroll
        for (int mf = 0; mf < 2; mf++) {
            int r = m0 + wm * 32 + mf * 16 + g;
#pragma unroll
            for (int nt = 0; nt < 8; nt++) {
                int col = n0 + wn * 64 + nt * 8 + t * 2;
                *(float2*)&C[(size_t)r * DM + col] =
                    make_float2(acc[mf][nt][0], acc[mf][nt][1]);
                *(float2*)&C[(size_t)(r + 8) * DM + col] =
                    make_float2(acc[mf][nt][2], acc[mf][nt][3]);
            }
        }
        return;
    }

#pragma unroll
    for (int mf = 0; mf < 2; mf++) {
#pragma unroll
        for (int hh = 0; hh < 2; hh++) {
            int row = m0 + wm * 32 + mf * 16 + g + hh * 8;
            int b = row >> 11;
            int s = row & (SEQ - 1);
#pragma unroll
            for (int nt = 0; nt < 8; nt++) {
                int col = n0 + wn * 64 + nt * 8 + t * 2;
                float v0 = acc[mf][nt][hh * 2 + 0];
                float v1 = acc[mf][nt][hh * 2 + 1];
                int d0 = col & 63;
                if (vmode != 3) {
                    int j0 = d0 & 31, j1 = (d0 + 1) & 31;
                    float2 cs0 = *(const float2*)&g_rope[((size_t)s * 32 + j0) * 2];
                    float2 cs1 = *(const float2*)&g_rope[((size_t)s * 32 + j1) * 2];
                    float o0 = v0 * cs0.x - v1 * cs0.y;
                    float o1 = v1 * cs1.x + v0 * cs1.y;
                    if (vmode == 1) { o0 *= QSCALE; o1 *= QSCALE; }
                    v0 = o0; v1 = o1;
                }
                int h = col >> 6;
                __half2 hv = __floats2half2_rn(v0, v1);
                if (vmode == 1)
                    *(__half2*)&g_q[(((size_t)b * NUM_HEADS + h) * SEQ + s) * HD + d0] = hv;
                else if (vmode == 2)
                    *(__half2*)&g_k[(((size_t)b * NUM_KV + h) * SEQ + s) * HD + d0] = hv;
                else
                    *(__half2*)&g_v[(((size_t)b * NUM_KV + h) * SEQ + s) * HD + d0] = hv;
            }
        }
    }
}

// ---------------------------------------------------------------------------
// fp16 mma flash attention v3: KV-split two-stream.
// 512 threads = 2 warp-groups of 8 warps. Group g processes KV tiles
// t === g (mod 2) with its own double-buffered K/V smem and its own named
// barrier, maintaining an independent online-softmax state (m,l,o). The two
// streams desynchronize naturally, so one group's mma overlaps the other's
// softmax on every SMSP. Exact merge at the end through smem.
// ---------------------------------------------------------------------------
#define FSTR 72
// smem: q [128][72] | k [2 groups][2 stages][64][72] | v same
#define FA_Q_ELE (128 * FSTR)
#define FA_KV_ELE (64 * FSTR)
#define FA_SMEM ((FA_Q_ELE + 8 * FA_KV_ELE) * 2)

__global__ __launch_bounds__(512, 1) void fa_f16()
{
    extern __shared__ __half sm[];
    __half* q_s = sm;

    const int tid = threadIdx.x, lane = tid & 31, wid = tid >> 5;
    const int grp = wid >> 3;            // warp-group 0/1
    const int wg  = wid & 7;             // warp within group -> Q rows wg*16
    const int ltid = tid & 255;          // thread within group
    const int g = lane >> 2, t = lane & 3;
    const int qs = ((int)gridDim.x - 1 - (int)blockIdx.x) * 128;  // heavy first
    const int h = blockIdx.y, b = blockIdx.z;
    const int kvh = h >> 2;

    const __half* qg = &g_q[(((size_t)b * NUM_HEADS + h) * SEQ + qs) * HD];
    const __half* kg = &g_k[(((size_t)b * NUM_KV + kvh) * SEQ) * HD];
    const __half* vg = &g_v[(((size_t)b * NUM_KV + kvh) * SEQ) * HD];

    const uint32_t sq = smem_u32(q_s);
    const uint32_t sk0 = sq + FA_Q_ELE * 2;            // k buffers base
    const uint32_t sv0 = sk0 + 4 * FA_KV_ELE * 2;      // v buffers base

    // ---- Q load (all 512 threads), then full sync so both groups see it ----
#pragma unroll
    for (int u = 0; u < 2; u++) {
        int c = tid + 512 * u;
        int r = c >> 3, q = c & 7;
        cp16(sq + (r * FSTR + q * 8) * 2, qg + (size_t)r * 64 + q * 8);
    }
    CP_COMMIT();
    CP_WAIT(0);
    __syncthreads();

    const int ntiles = qs / 64 + 2;
    // this group's tiles: t = grp, grp+2, ...  j-th own tile -> stage j&1
    const int nown = (ntiles - grp + 1) >> 1;

    auto issue_kv = [&](int j) {      // load own tile j (global tile grp+2j)
        if (j >= nown) return;
        int koff = (grp + 2 * j) * 64;
        int st = j & 1;
        uint32_t kb = sk0 + (grp * 2 + st) * FA_KV_ELE * 2;
        uint32_t vb = sv0 + (grp * 2 + st) * FA_KV_ELE * 2;
#pragma unroll
        for (int u = 0; u < 2; u++) {
            int c = ltid + 256 * u;
            int r = c >> 3, q = c & 7;
            cp16(kb + (r * FSTR + q * 8) * 2, kg + (size_t)(koff + r) * 64 + q * 8);
            cp16(vb + (r * FSTR + q * 8) * 2, vg + (size_t)(koff + r) * 64 + q * 8);
        }
    };

    issue_kv(0); CP_COMMIT();
    issue_kv(1); CP_COMMIT();

    float o[8][4];
#pragma unroll
    for (int p = 0; p < 8; p++)
#pragma unroll
        for (int r = 0; r < 4; r++) o[p][r] = 0.f;
    float m0r = -1e30f, m1r = -1e30f, l0 = 0.f, l1 = 0.f;
    uint32_t qf[4][4];
#pragma unroll
    for (int kc = 0; kc < 4; kc++)
        ldmx4(qf[kc], sq + ((wg * 16 + (lane & 15)) * FSTR +
                            kc * 16 + (lane >> 4) * 8) * 2);

    const int barid = 1 + grp;

    for (int j = 0; j < nown; j++) {
        CP_WAIT(1);
        BARG(barid);
        const int st = j & 1;
        const uint32_t kb = sk0 + (grp * 2 + st) * FA_KV_ELE * 2;
        const uint32_t vb = sv0 + (grp * 2 + st) * FA_KV_ELE * 2;

        // S = Q @ K^T (scale pre-folded into Q)
        float s[8][4];
#pragma unroll
        for (int p = 0; p < 8; p++)
#pragma unroll
            for (int r = 0; r < 4; r++) s[p][r] = 0.f;
#pragma unroll
        for (int kc = 0; kc < 4; kc++) {
#pragma unroll
            for (int p = 0; p < 4; p++) {
                uint32_t r[4];
                ldmx4(r, kb + ((p * 16 + (lane & 7) + ((lane >> 4) & 1) * 8) * FSTR +
                               kc * 16 + ((lane >> 3) & 1) * 8) * 2);
                mma_f16(s[2 * p], qf[kc], r);
                mma_f16(s[2 * p + 1], qf[kc], r + 2);
            }
        }

        // causal mask on boundary tiles
        const int kt = (grp + 2 * j) * 64;
        const int rowg = qs + wg * 16 + g;
        if (kt + 63 > qs + wg * 16) {
#pragma unroll
            for (int p = 0; p < 8; p++) {
                int col = kt + p * 8 + 2 * t;
                if (col > rowg)     s[p][0] = -1e30f;
                if (col + 1 > rowg) s[p][1] = -1e30f;
                if (col > rowg + 8)     s[p][2] = -1e30f;
                if (col + 1 > rowg + 8) s[p][3] = -1e30f;
            }
        }

        // online softmax (rows g and g+8), quad reductions
        float mx0 = -1e30f, mx1 = -1e30f;
#pragma unroll
        for (int p = 0; p < 8; p++) {
            mx0 = fmaxf(mx0, fmaxf(s[p][0], s[p][1]));
            mx1 = fmaxf(mx1, fmaxf(s[p][2], s[p][3]));
        }
        mx0 = fmaxf(mx0, __shfl_xor_sync(0xffffffffu, mx0, 1));
        mx0 = fmaxf(mx0, __shfl_xor_sync(0xffffffffu, mx0, 2));
        mx1 = fmaxf(mx1, __shfl_xor_sync(0xffffffffu, mx1, 1));
        mx1 = fmaxf(mx1, __shfl_xor_sync(0xffffffffu, mx1, 2));
        float mn0 = fmaxf(m0r, mx0), mn1 = fmaxf(m1r, mx1);
        float a0 = ex2(m0r - mn0), a1 = ex2(m1r - mn1);
        m0r = mn0; m1r = mn1;

        __half2 acc0 = __floats2half2_rn(0.f, 0.f);
        __half2 acc1 = acc0;
        uint32_t pf[4][4];
#pragma unroll
        for (int p = 0; p < 8; p++) {
            uint32_t e0 = ex2h2(packh2(s[p][0] - mn0, s[p][1] - mn0));
            uint32_t e1 = ex2h2(packh2(s[p][2] - mn1, s[p][3] - mn1));
            acc0 = __hadd2(acc0, *reinterpret_cast<__half2*>(&e0));
            acc1 = __hadd2(acc1, *reinterpret_cast<__half2*>(&e1));
            int kc = p >> 1;
            if ((p & 1) == 0) { pf[kc][0] = e0; pf[kc][1] = e1; }
            else              { pf[kc][2] = e0; pf[kc][3] = e1; }
        }
        float ps0 = __low2float(acc0) + __high2float(acc0);
        float ps1 = __low2float(acc1) + __high2float(acc1);
        ps0 += __shfl_xor_sync(0xffffffffu, ps0, 1);
        ps0 += __shfl_xor_sync(0xffffffffu, ps0, 2);
        ps1 += __shfl_xor_sync(0xffffffffu, ps1, 1);
        ps1 += __shfl_xor_sync(0xffffffffu, ps1, 2);
        l0 = l0 * a0 + ps0;
        l1 = l1 * a1 + ps1;
#pragma unroll
        for (int p = 0; p < 8; p++) {
            o[p][0] *= a0; o[p][1] *= a0;
            o[p][2] *= a1; o[p][3] *= a1;
        }

        // O += P @ V
#pragma unroll
        for (int kc = 0; kc < 4; kc++) {
#pragma unroll
            for (int p = 0; p < 4; p++) {
                uint32_t r[4];
                ldmx4t(r, vb + ((kc * 16 + (lane & 15)) * FSTR +
                                p * 16 + ((lane >> 4) & 1) * 8) * 2);
                mma_f16(o[2 * p], pf[kc], r);
                mma_f16(o[2 * p + 1], pf[kc], r + 2);
            }
        }

        BARG(barid);
        issue_kv(j + 2);
        CP_COMMIT();
    }

    // ---- merge the two streams ----
    __syncthreads();   // all compute done; smem free for reuse
    float* fb = (float*)(sm + FA_Q_ELE);   // 36,864B scratch (k region)
    const int midx = (wg * 32 + lane) * 36;
    if (grp == 1) {
#pragma unroll
        for (int p = 0; p < 8; p++) {
            fb[midx + p * 4 + 0] = o[p][0];
            fb[midx + p * 4 + 1] = o[p][1];
            fb[midx + p * 4 + 2] = o[p][2];
            fb[midx + p * 4 + 3] = o[p][3];
        }
        fb[midx + 32] = m0r;
        fb[midx + 33] = m1r;
        fb[midx + 34] = l0;
        fb[midx + 35] = l1;
    }
    __syncthreads();
    if (grp == 0) {
        float bm0 = fb[midx + 32], bm1 = fb[midx + 33];
        float bl0 = fb[midx + 34], bl1 = fb[midx + 35];
        float M0 = fmaxf(m0r, bm0), M1 = fmaxf(m1r, bm1);
        float a0 = ex2(m0r - M0), b0 = ex2(bm0 - M0);
        float a1 = ex2(m1r - M1), b1 = ex2(bm1 - M1);
        float inv0 = 1.f / (l0 * a0 + bl0 * b0);
        float inv1 = 1.f / (l1 * a1 + bl1 * b1);
        __half* og = &g_ao[((size_t)(b * SEQ + qs + wg * 16)) * DM + h * HD];
#pragma unroll
        for (int p = 0; p < 8; p++) {
            int col = p * 8 + 2 * t;
            float v0 = (o[p][0] * a0 + fb[midx + p * 4 + 0] * b0) * inv0;
            float v1 = (o[p][1] * a0 + fb[midx + p * 4 + 1] * b0) * inv0;
            float v2 = (o[p][2] * a1 + fb[midx + p * 4 + 2] * b1) * inv1;
            float v3 = (o[p][3] * a1 + fb[midx + p * 4 + 3] * b1) * inv1;
            *(__half2*)&og[(size_t)g * DM + col] = __floats2half2_rn(v0, v1);
            *(__half2*)&og[(size_t)(g + 8) * DM + col] = __floats2half2_rn(v2, v3);
        }
    }
}

// ---------------------------------------------------------------------------

extern "C" void kernel_launch(void* const* d_in, const int* in_sizes, int n_in,
                              void* d_out, int out_size)
{
    const float* x  = (const float*)d_in[0];
    const float* Wq = (const float*)d_in[2];
    const float* Wk = (const float*)d_in[3];
    const float* Wv = (const float*)d_in[4];
    const float* Wo = (const float*)d_in[5];
    float* out = (float*)d_out;

    void *xh, *wq, *wk, *wv, *wo, *ao;
    cudaGetSymbolAddress(&xh, g_xh);
    cudaGetSymbolAddress(&wq, g_wq);
    cudaGetSymbolAddress(&wk, g_wk);
    cudaGetSymbolAddress(&wv, g_wv);
    cudaGetSymbolAddress(&wo, g_wo);
    cudaGetSymbolAddress(&ao, g_ao);

    cudaFuncSetAttribute(gemm_f16, cudaFuncAttributeMaxDynamicSharedMemorySize, GSMEM);
    cudaFuncSetAttribute(fa_f16, cudaFuncAttributeMaxDynamicSharedMemorySize, FA_SMEM);

    // fused prologue: all conversions + rope table (one launch)
    prep<<<18688, 256>>>((const float4*)x, (const float4*)Wq, (const float4*)Wk,
                         (const float4*)Wv, (const float4*)Wo);

    // fused Q+K+V projections (RoPE on Q/K, scale folded into Q)
    gemm_f16<<<dim3(24, MTOT / 128), 256, GSMEM>>>(
        (const __half*)xh, (const __half*)wq, (const __half*)wk,
        (const __half*)wv, nullptr, DM, 4);

    // flash attention (two-stream KV-split, heavy-first)
    fa_f16<<<dim3(SEQ / 128, NUM_HEADS, B_DIM), 512, FA_SMEM>>>();

    // output projection
    gemm_f16<<<dim3(DM / 128, MTOT / 128), 256, GSMEM>>>(
        (const __half*)ao, (const __half*)wo, nullptr, nullptr, out, DM, 0);
}